// round 14
// baseline (speedup 1.0000x reference)
#include <cuda_runtime.h>
#include <math.h>
#include <stdint.h>

// ---------------- problem constants ----------------
#define TT      512          // sequence length
#define UDIM    512          // LSTM hidden
#define NGATE   2048         // 4*U
#define XDIM    250          // word(200)+tag(50)
#define HID     1024
#define NSP     8192         // spans per head
#define KS_     4
#define KL_     3
#define TSZ     (TT*HID)     // one P table
#define GDIR    32           // CTAs per LSTM direction
#define UPC     16           // units per CTA (512/32)

// ---------------- device scratch (static; no allocation allowed) ----------------
__device__ float g_x   [TT*XDIM];
__device__ float g_xg  [4*TT*NGATE];     // gate preactivations per direction
__device__ float g_P   [14*TSZ];         // factorized span tables
__device__ float g_loss;
__device__ unsigned g_gen;               // epoch counter (per launch/replay)
__device__ unsigned g_tktA, g_tktB;      // gemm tile tickets
// tagged h exchange buffers: slot = { f32 h (lo), u32 tag (hi) }
__device__ __align__(16) unsigned long long g_hxF[TT*UDIM];
__device__ __align__(16) unsigned long long g_hxB[TT*UDIM];

// ---------------- fast activations ----------------
__device__ __forceinline__ float fsigmoid(float x) {
    return __fdividef(1.f, 1.f + __expf(-x));
}
__device__ __forceinline__ float ftanh(float x) {
    return __fdividef(2.f, 1.f + __expf(-2.f * x)) - 1.f;
}

// verified tagged-slot pair load: data rides with tag in the same 8B word
__device__ __forceinline__ void ld_slot_pair(const unsigned long long* p, unsigned tg,
                                             float& o0, float& o1) {
    unsigned long long x, y;
    for (;;) {
        asm volatile("ld.volatile.global.v2.u64 {%0,%1}, [%2];"
                     : "=l"(x), "=l"(y) : "l"(p) : "memory");
        if ((unsigned)(x >> 32) >= tg && (unsigned)(y >> 32) >= tg) break;
    }
    o0 = __uint_as_float((unsigned)x);
    o1 = __uint_as_float((unsigned)y);
}

// ---------------- misc kernels ----------------
__global__ void build_x_kernel(const int* __restrict__ wi, const int* __restrict__ ti,
                               const float* __restrict__ Ww, const float* __restrict__ Wt) {
    int t = blockIdx.x;
    int j = threadIdx.x;
    if (t == 0 && j == 0) { g_loss = 0.f; g_gen += 1u; g_tktA = 0u; g_tktB = 0u; }
    if (j < 200)      g_x[t*XDIM + j] = Ww[(size_t)wi[t]*200 + j];
    else if (j < XDIM) g_x[t*XDIM + j] = Wt[(size_t)ti[t]*50 + (j - 200)];
}

__global__ void finalize_kernel(float* out) {
    out[0] = g_loss * (1.0f / 16384.0f);
}

// ---------------- standalone batched SGEMM (layer0 xg only) ----------------
struct GemmDesc {
    const float* A; const float* B; float* C; const float* bias;
    int M, N, K, lda, ldb, ldc;
};
struct GemmBatch { GemmDesc d[2]; };

__global__ void __launch_bounds__(256)
sgemm_kernel(GemmBatch batch)
{
    GemmDesc g = batch.d[blockIdx.z];
    const int m0 = blockIdx.y * 128;
    const int n0 = blockIdx.x * 128;
    if (m0 >= g.M || n0 >= g.N) return;

    __shared__ __align__(16) float As[16][132];
    __shared__ __align__(16) float Bs[16][132];

    const int tid = threadIdx.x;
    const int tx = tid & 15;
    const int ty = tid >> 4;

    unsigned long long acc2[8][4];
    #pragma unroll
    for (int i = 0; i < 8; i++)
        #pragma unroll
        for (int j = 0; j < 4; j++) acc2[i][j] = 0ull;

    const int lr = tid >> 1;
    const int lk = (tid & 1) * 8;

    for (int k0 = 0; k0 < g.K; k0 += 16) {
        {
            const float* ap = g.A + (size_t)(m0 + lr) * g.lda + k0 + lk;
            #pragma unroll
            for (int q = 0; q < 8; q++) {
                float v = (k0 + lk + q < g.K) ? ap[q] : 0.f;
                As[lk + q][lr] = v;
            }
            const float* bp = g.B + (size_t)(n0 + lr) * g.ldb + k0 + lk;
            #pragma unroll
            for (int q = 0; q < 8; q++) {
                float v = (k0 + lk + q < g.K) ? bp[q] : 0.f;
                Bs[lk + q][lr] = v;
            }
        }
        __syncthreads();

        #pragma unroll
        for (int kk = 0; kk < 16; kk++) {
            float a[8];
            *(float4*)&a[0] = *(const float4*)&As[kk][ty * 8];
            *(float4*)&a[4] = *(const float4*)&As[kk][ty * 8 + 4];
            const unsigned long long* bp = (const unsigned long long*)&Bs[kk][tx * 8];
            unsigned long long bv[4];
            #pragma unroll
            for (int j = 0; j < 4; j++) bv[j] = bp[j];
            #pragma unroll
            for (int i = 0; i < 8; i++) {
                unsigned long long av;
                asm("mov.b64 %0, {%1, %1};" : "=l"(av) : "f"(a[i]));
                #pragma unroll
                for (int j = 0; j < 4; j++)
                    asm("fma.rn.f32x2 %0, %1, %2, %0;" : "+l"(acc2[i][j]) : "l"(av), "l"(bv[j]));
            }
        }
        __syncthreads();
    }

    #pragma unroll
    for (int i = 0; i < 8; i++) {
        float* cp = g.C + (size_t)(m0 + ty * 8 + i) * g.ldc + n0 + tx * 8;
        float o[8];
        #pragma unroll
        for (int j = 0; j < 4; j++)
            asm("mov.b64 {%0, %1}, %2;" : "=f"(o[2*j]), "=f"(o[2*j+1]) : "l"(acc2[i][j]));
        if (g.bias) {
            #pragma unroll
            for (int j = 0; j < 8; j++) o[j] += g.bias[n0 + tx * 8 + j];
        }
        *(float4*)cp       = *(float4*)&o[0];
        *(float4*)(cp + 4) = *(float4*)&o[4];
    }
}

// ---------------- fused persistent kernel: LSTM CTAs + dependent GEMM CTAs ----------------
struct PTab {
    const float* B[14];
    float*       C[14];
    int          ldb[14];
};

__global__ void __launch_bounds__(512, 1)
fused_kernel(int phase,
             const float* __restrict__ xgF, const float* __restrict__ xgB,
             const float* __restrict__ WhhF, const float* __restrict__ WhhB,
             const float* __restrict__ WB0, const float* __restrict__ WB1,
             const float* __restrict__ bias0, const float* __restrict__ bias1,
             float* C0, float* C1, PTab pt)
{
    __shared__ __align__(16) float sA[16][136];   // GEMM: A tile
    __shared__ __align__(16) float sB[16][136];   // GEMM: B tile
    __shared__ __align__(16) float hsm[2][UDIM];  // LSTM: staged h (db)
    __shared__ __align__(16) float part[2][8][64];// LSTM: partials (db)
    __shared__ int smy;

    const int tid = threadIdx.x;
    const unsigned gen = g_gen;
    const unsigned base = ((gen * 2u + (unsigned)phase) << 10);

    if (blockIdx.x < 2 * GDIR) {
        // ================= LSTM role =================
        const int bid  = blockIdx.x;
        const bool back = (bid >= GDIR);
        const int dd    = back ? bid - GDIR : bid;

        const float* xg  = back ? xgB  : xgF;
        const float* Whh = back ? WhhB : WhhF;
        unsigned long long* hx = back ? g_hxB : g_hxF;

        const int wid   = tid >> 5;
        const int lane  = tid & 31;
        const int chunk = wid & 7;
        const int rg    = wid >> 3;
        const int row   = rg * 32 + lane;   // gate*16 + unit_local
        const int gate  = row >> 4;
        const int ul    = row & 15;
        const int u0    = dd * UPC;
        const int grow  = gate * UDIM + u0 + ul;

        unsigned long long w[32];
        {
            const ulonglong2* wp = (const ulonglong2*)(Whh + (size_t)grow * UDIM + chunk * 64);
            #pragma unroll
            for (int q = 0; q < 16; q++) {
                ulonglong2 v = wp[q];
                w[2*q]   = v.x;
                w[2*q+1] = v.y;
            }
        }

        // reduce/publish role: warps 14,15 (tid >= 448)
        const bool isred = (tid >= 448);
        const int rtid = tid - 448;
        const int ru  = rtid >> 2;           // unit 0..15
        const int rgt = rtid & 3;            // gate 0..3

        float c = 0.f;

        for (int s = 0; s < TT; s++) {
            const int t = back ? (TT - 1 - s) : s;
            const int p = s & 1;

            float xgv = 0.f;
            if (isred)
                xgv = __ldg(xg + (size_t)t * NGATE + rgt * UDIM + u0 + ru);

            unsigned long long a0 = 0ull, a1 = 0ull;
            if (s > 0) {
                const int tp = back ? t + 1 : t - 1;
                if (rg == 0) {
                    const unsigned long long* src = hx + (size_t)tp * UDIM + chunk * 64 + lane * 2;
                    const unsigned target = base + (unsigned)s;
                    unsigned long long x0, y0, x1, y1;
                    asm volatile("ld.volatile.global.v2.u64 {%0,%1}, [%2];"
                                 : "=l"(x0), "=l"(y0) : "l"(src) : "memory");
                    bool ok = ((unsigned)(x0 >> 32) >= target) && ((unsigned)(y0 >> 32) >= target);
                    if (!__all_sync(0xffffffffu, ok)) {
                        for (;;) {
                            asm volatile("ld.volatile.global.v2.u64 {%0,%1}, [%2];"
                                         : "=l"(x1), "=l"(y1) : "l"(src) : "memory");
                            ok = ((unsigned)(x0 >> 32) >= target) && ((unsigned)(y0 >> 32) >= target);
                            if (__all_sync(0xffffffffu, ok)) break;
                            asm volatile("ld.volatile.global.v2.u64 {%0,%1}, [%2];"
                                         : "=l"(x0), "=l"(y0) : "l"(src) : "memory");
                            ok = ((unsigned)(x1 >> 32) >= target) && ((unsigned)(y1 >> 32) >= target);
                            if (__all_sync(0xffffffffu, ok)) { x0 = x1; y0 = y1; break; }
                        }
                    }
                    float2 hv = make_float2(__uint_as_float((unsigned)x0),
                                            __uint_as_float((unsigned)y0));
                    *(float2*)&hsm[p][chunk * 64 + lane * 2] = hv;
                }
                asm volatile("bar.sync %0, 64;" :: "r"(chunk + 1) : "memory");

                const ulonglong2* hq = (const ulonglong2*)&hsm[p][chunk * 64];
                #pragma unroll
                for (int q = 0; q < 16; q++) {
                    ulonglong2 hv = hq[q];
                    asm("fma.rn.f32x2 %0, %1, %2, %0;" : "+l"(a0) : "l"(w[2*q]),   "l"(hv.x));
                    asm("fma.rn.f32x2 %0, %1, %2, %0;" : "+l"(a1) : "l"(w[2*q+1]), "l"(hv.y));
                }
            }
            float l0, h0, l1, h1;
            asm("mov.b64 {%0, %1}, %2;" : "=f"(l0), "=f"(h0) : "l"(a0));
            asm("mov.b64 {%0, %1}, %2;" : "=f"(l1), "=f"(h1) : "l"(a1));
            part[p][chunk][row] = (l0 + h0) + (l1 + h1);

            if (isred) {
                asm volatile("bar.sync 9, 512;" ::: "memory");
                const int prow = rgt * 16 + ru;
                float v = xgv;
                #pragma unroll
                for (int cc = 0; cc < 8; cc++) v += part[p][cc][prow];
                float v1 = __shfl_down_sync(0xffffffffu, v, 1);
                float v2 = __shfl_down_sync(0xffffffffu, v, 2);
                float v3 = __shfl_down_sync(0xffffffffu, v, 3);
                if (rgt == 0) {
                    float iv = fsigmoid(v);
                    float fv = fsigmoid(v1);
                    float gv = ftanh(v2);
                    float ov = fsigmoid(v3);
                    c = fv * c + iv * gv;
                    float h = ov * ftanh(c);
                    unsigned long long pkt = (unsigned long long)__float_as_uint(h)
                                           | ((unsigned long long)(base + (unsigned)s + 1u) << 32);
                    unsigned long long* dst = hx + (size_t)t * UDIM + u0 + ru;
                    asm volatile("st.relaxed.gpu.global.u64 [%0], %1;" :: "l"(dst), "l"(pkt) : "memory");
                }
            } else {
                asm volatile("bar.arrive 9, 512;" ::: "memory");
            }
        }
        return;
    }

    // ================= GEMM role =================
    const int NT = (phase == 0) ? 128 : 448;
    unsigned* tkt = (phase == 0) ? &g_tktA : &g_tktB;

    const int tx = tid & 15;
    const int ty = tid >> 4;          // 0..31
    const int lr = tid >> 2;          // 0..127
    const int lk4 = (tid & 3) * 4;

    for (;;) {
        if (tid == 0) smy = (int)atomicAdd(tkt, 1u);
        __syncthreads();
        const int my = smy;
        __syncthreads();
        if (my >= NT) return;

        int m0, n0, K, ldb, ldc, isfwd = 1;
        const float* Bw; float* C; const float* bias;

        if (phase == 0) {
            int cls = my >> 6, idx = my & 63;
            int dir = idx >> 5, r = idx & 31, mi = r >> 4;
            int mt = (cls == 0) ? (mi ? 2 : 1) : (mi ? 3 : 0);
            m0 = mt * 128; n0 = (r & 15) * 128;
            K = 1024; ldb = 1024; ldc = NGATE;
            Bw = dir ? WB1 : WB0;
            bias = dir ? bias1 : bias0;
            C = dir ? C1 : C0;
        } else {
            int cls = my / 112, idx = my % 112;
            int desc;
            if (idx < 56) {
                const int fl[7] = {0, 1, 2, 3, 8, 9, 10};
                desc = fl[idx >> 3]; m0 = cls * 128; isfwd = 1;
            } else {
                const int bl[7] = {4, 5, 6, 7, 11, 12, 13};
                desc = bl[(idx - 56) >> 3]; m0 = (3 - cls) * 128; isfwd = 0;
            }
            n0 = (idx & 7) * 128;
            K = 512; ldb = pt.ldb[desc]; ldc = HID;
            Bw = pt.B[desc]; C = pt.C[desc]; bias = nullptr;
        }

        // sentinel: wait until this tile's rows are (almost surely) published
        if (phase == 0) {
            const unsigned tgF = base + (unsigned)(m0 + 127) + 1u;
            const unsigned tgB = base + 512u - (unsigned)m0;
            volatile const unsigned long long* sf =
                (volatile const unsigned long long*)(g_hxF + (size_t)(m0 + 127) * UDIM + tid);
            volatile const unsigned long long* sb =
                (volatile const unsigned long long*)(g_hxB + (size_t)m0 * UDIM + tid);
            while (!(((unsigned)((*sf) >> 32) >= tgF) && ((unsigned)((*sb) >> 32) >= tgB)))
                __nanosleep(200);
        } else {
            const unsigned tg = isfwd ? (base + (unsigned)(m0 + 127) + 1u)
                                      : (base + 512u - (unsigned)m0);
            volatile const unsigned long long* sp = (volatile const unsigned long long*)
                ((isfwd ? g_hxF : g_hxB) + (size_t)(isfwd ? m0 + 127 : m0) * UDIM + tid);
            while (!((unsigned)((*sp) >> 32) >= tg))
                __nanosleep(200);
        }
        __syncthreads();

        unsigned long long acc2[4][4];
        #pragma unroll
        for (int i = 0; i < 4; i++)
            #pragma unroll
            for (int j = 0; j < 4; j++) acc2[i][j] = 0ull;

        const int t = m0 + lr;
        for (int k0 = 0; k0 < K; k0 += 16) {
            // A stage from tagged slots (per-slot verified)
            {
                const int unit = k0 + lk4;
                const unsigned long long* src; unsigned tg;
                if (phase == 0) {
                    if (unit < 512) { src = g_hxF + (size_t)t * UDIM + unit;       tg = base + t + 1; }
                    else            { src = g_hxB + (size_t)t * UDIM + unit - 512; tg = base + 512 - t; }
                } else {
                    src = (isfwd ? g_hxF : g_hxB) + (size_t)t * UDIM + unit;
                    tg = isfwd ? (base + t + 1) : (base + 512 - t);
                }
                float a0, a1, a2, a3;
                ld_slot_pair(src,     tg, a0, a1);
                ld_slot_pair(src + 2, tg, a2, a3);
                sA[lk4 + 0][lr] = a0;
                sA[lk4 + 1][lr] = a1;
                sA[lk4 + 2][lr] = a2;
                sA[lk4 + 3][lr] = a3;
            }
            // B stage (plain weights)
            {
                float4 bv = *(const float4*)(Bw + (size_t)(n0 + lr) * ldb + k0 + lk4);
                sB[lk4 + 0][lr] = bv.x;
                sB[lk4 + 1][lr] = bv.y;
                sB[lk4 + 2][lr] = bv.z;
                sB[lk4 + 3][lr] = bv.w;
            }
            __syncthreads();

            #pragma unroll
            for (int kk = 0; kk < 16; kk++) {
                float4 a4 = *(const float4*)&sA[kk][ty * 4];
                ulonglong2 b01 = *(const ulonglong2*)&sB[kk][tx * 8];
                ulonglong2 b23 = *(const ulonglong2*)&sB[kk][tx * 8 + 4];
                unsigned long long bv[4] = {b01.x, b01.y, b23.x, b23.y};
                float a[4] = {a4.x, a4.y, a4.z, a4.w};
                #pragma unroll
                for (int i = 0; i < 4; i++) {
                    unsigned long long av;
                    asm("mov.b64 %0, {%1, %1};" : "=l"(av) : "f"(a[i]));
                    #pragma unroll
                    for (int j = 0; j < 4; j++)
                        asm("fma.rn.f32x2 %0, %1, %2, %0;" : "+l"(acc2[i][j]) : "l"(av), "l"(bv[j]));
                }
            }
            __syncthreads();
        }

        #pragma unroll
        for (int i = 0; i < 4; i++) {
            float* cp = C + (size_t)(m0 + ty * 4 + i) * ldc + n0 + tx * 8;
            float o[8];
            #pragma unroll
            for (int j = 0; j < 4; j++)
                asm("mov.b64 {%0, %1}, %2;" : "=f"(o[2*j]), "=f"(o[2*j+1]) : "l"(acc2[i][j]));
            if (bias) {
                #pragma unroll
                for (int j = 0; j < 8; j++) o[j] += bias[n0 + tx * 8 + j];
            }
            *(float4*)cp       = *(float4*)&o[0];
            *(float4*)(cp + 4) = *(float4*)&o[4];
        }
    }
}

// ---------------- span loss: warp per span (G spans per warp), gather from P tables ----------------
template<int KF, int NC, int G>
__global__ void __launch_bounds__(256)
span_kernel(const int* __restrict__ lefts, const int* __restrict__ rights,
            const int* __restrict__ targets,
            const float* __restrict__ b1, const float* __restrict__ W2,
            const float* __restrict__ b2, int tabF, int tabB)
{
    const int lane = threadIdx.x & 31;
    const int wInB = threadIdx.x >> 5;
    const int warp0 = (blockIdx.x * 8 + wInB) * G;

    float lsum = 0.f;

    for (int g = 0; g < G; g++) {
        const int warp = warp0 + g;

        float4 acc[8];
        #pragma unroll
        for (int m = 0; m < 8; m++)
            acc[m] = *(const float4*)(b1 + m * 128 + lane * 4);

        int ls[KF], rs[KF];
        #pragma unroll
        for (int k = 0; k < KF; k++) {
            ls[k] = __ldg(lefts  + (size_t)warp * KF + k);
            rs[k] = __ldg(rights + (size_t)warp * KF + k);
        }

        #pragma unroll
        for (int k = 0; k < KF; k++) {
            const float* Pf = g_P + (size_t)(tabF + k) * TSZ;
            const float* Pb = g_P + (size_t)(tabB + k) * TSZ;
            const float* r0 = Pf + (size_t)rs[k]       * HID + lane * 4;
            const float* r1 = Pf + (size_t)(ls[k] - 1) * HID + lane * 4;
            const float* r2 = Pb + (size_t)ls[k]       * HID + lane * 4;
            const float* r3 = Pb + (size_t)(rs[k] + 1) * HID + lane * 4;
            #pragma unroll
            for (int m = 0; m < 8; m++) {
                float4 va = __ldg((const float4*)(r0 + m * 128));
                float4 vb = __ldg((const float4*)(r1 + m * 128));
                float4 vc = __ldg((const float4*)(r2 + m * 128));
                float4 vd = __ldg((const float4*)(r3 + m * 128));
                acc[m].x += (va.x - vb.x) + (vc.x - vd.x);
                acc[m].y += (va.y - vb.y) + (vc.y - vd.y);
                acc[m].z += (va.z - vb.z) + (vc.z - vd.z);
                acc[m].w += (va.w - vb.w) + (vc.w - vd.w);
            }
        }
        #pragma unroll
        for (int m = 0; m < 8; m++) {
            acc[m].x = fmaxf(acc[m].x, 0.f);
            acc[m].y = fmaxf(acc[m].y, 0.f);
            acc[m].z = fmaxf(acc[m].z, 0.f);
            acc[m].w = fmaxf(acc[m].w, 0.f);
        }

        const int tgt = __ldg(targets + warp);
        float mx = -1e30f, ssum = 0.f, sct = 0.f;
        for (int s = 0; s < NC; s++) {
            const float* wr = W2 + (size_t)s * HID + lane * 4;
            float p = 0.f;
            #pragma unroll
            for (int m = 0; m < 8; m++) {
                float4 wv = __ldg((const float4*)(wr + m * 128));
                p += wv.x * acc[m].x + wv.y * acc[m].y + wv.z * acc[m].z + wv.w * acc[m].w;
            }
            p += __shfl_xor_sync(0xffffffffu, p, 1);
            p += __shfl_xor_sync(0xffffffffu, p, 2);
            p += __shfl_xor_sync(0xffffffffu, p, 4);
            p += __shfl_xor_sync(0xffffffffu, p, 8);
            p += __shfl_xor_sync(0xffffffffu, p, 16);
            p += b2[s];
            if (s == tgt) sct = p;
            float m2 = fmaxf(mx, p);
            ssum = ssum * expf(mx - m2) + expf(p - m2);
            mx = m2;
        }
        lsum += mx + logf(ssum) - sct;
    }

    __shared__ float smloss[8];
    if (lane == 0) smloss[wInB] = lsum;
    __syncthreads();
    if (threadIdx.x == 0) {
        float s = 0.f;
        #pragma unroll
        for (int q = 0; q < 8; q++) s += smloss[q];
        atomicAdd(&g_loss, s);
    }
}

// ---------------- host launch ----------------
extern "C" void kernel_launch(void* const* d_in, const int* in_sizes, int n_in,
                              void* d_out, int out_size)
{
    (void)n_in; (void)out_size;
    const int* wi = (const int*)d_in[0];
    const int* ti = (const int*)d_in[1];

    int isl, isr, ist, ill, ilr, ilt;
    if (in_sizes[2] == NSP) {
        ist = 2; ilt = 3; isl = 4; isr = 5; ill = 6; ilr = 7;
    } else {
        isl = 2; isr = 3; ist = 4; ill = 5; ilr = 6; ilt = 7;
    }

    const float* Wih[4] = {(const float*)d_in[10], (const float*)d_in[13],
                           (const float*)d_in[16], (const float*)d_in[19]};
    const float* Whh[4] = {(const float*)d_in[11], (const float*)d_in[14],
                           (const float*)d_in[17], (const float*)d_in[20]};
    const float* bb [4] = {(const float*)d_in[12], (const float*)d_in[15],
                           (const float*)d_in[18], (const float*)d_in[21]};
    const float* Ws1 = (const float*)d_in[22];
    const float* bs1 = (const float*)d_in[23];
    const float* Ws2 = (const float*)d_in[24];
    const float* bs2 = (const float*)d_in[25];
    const float* Wl1 = (const float*)d_in[26];
    const float* bl1 = (const float*)d_in[27];
    const float* Wl2 = (const float*)d_in[28];
    const float* bl2 = (const float*)d_in[29];

    float *px, *pxg, *pP;
    cudaGetSymbolAddress((void**)&px,  g_x);
    cudaGetSymbolAddress((void**)&pxg, g_xg);
    cudaGetSymbolAddress((void**)&pP,  g_P);

    build_x_kernel<<<TT, 256>>>(wi, ti, (const float*)d_in[8], (const float*)d_in[9]);

    // layer0 gate preactivations: xg = x @ Wih^T + b
    {
        GemmBatch gb = {};
        for (int d = 0; d < 2; d++)
            gb.d[d] = { px, Wih[d], pxg + (size_t)d * TT * NGATE, bb[d],
                        TT, NGATE, XDIM, XDIM, XDIM, NGATE };
        sgemm_kernel<<<dim3(16, 4, 2), 256>>>(gb);
    }

    PTab ptEmpty = {};
    // kernel A: L0 LSTM + xg1 GEMM (consumes tagged H0)
    fused_kernel<<<64 + 128, 512>>>(0,
        pxg, pxg + (size_t)TT * NGATE, Whh[0], Whh[1],
        Wih[2], Wih[3], bb[2], bb[3],
        pxg + (size_t)2 * TT * NGATE, pxg + (size_t)3 * TT * NGATE, ptEmpty);

    // kernel B: L1 LSTM + P-table GEMMs (consume tagged OUT)
    PTab pt = {};
    for (int k = 0; k < KS_; k++) {
        pt.B[k]      = Ws1 + k * 512;         pt.C[k]      = pP + (size_t)k * TSZ;        pt.ldb[k]      = 4096;
        pt.B[4 + k]  = Ws1 + 2048 + k * 512;  pt.C[4 + k]  = pP + (size_t)(4 + k) * TSZ;  pt.ldb[4 + k]  = 4096;
    }
    for (int k = 0; k < KL_; k++) {
        pt.B[8 + k]  = Wl1 + k * 512;         pt.C[8 + k]  = pP + (size_t)(8 + k) * TSZ;  pt.ldb[8 + k]  = 3072;
        pt.B[11 + k] = Wl1 + 1536 + k * 512;  pt.C[11 + k] = pP + (size_t)(11 + k) * TSZ; pt.ldb[11 + k] = 3072;
    }
    fused_kernel<<<64 + 448, 512>>>(1,
        pxg + (size_t)2 * TT * NGATE, pxg + (size_t)3 * TT * NGATE, Whh[2], Whh[3],
        nullptr, nullptr, nullptr, nullptr, nullptr, nullptr, pt);

    // struct head: W2 tiny (2x1024) -> G=1; label head: W2 = 56x1024 -> G=4 for L1/L2 reuse
    span_kernel<KS_, 2,  1><<<NSP / 8,  256>>>((const int*)d_in[isl], (const int*)d_in[isr],
                                               (const int*)d_in[ist], bs1, Ws2, bs2, 0, 4);
    span_kernel<KL_, 56, 4><<<NSP / 32, 256>>>((const int*)d_in[ill], (const int*)d_in[ilr],
                                               (const int*)d_in[ilt], bl1, Wl2, bl2, 8, 11);

    finalize_kernel<<<1, 1>>>((float*)d_out);
}

// round 15
// speedup vs baseline: 1.0382x; 1.0382x over previous
#include <cuda_runtime.h>
#include <math.h>
#include <stdint.h>

// ---------------- problem constants ----------------
#define TT      512          // sequence length
#define UDIM    512          // LSTM hidden
#define NGATE   2048         // 4*U
#define XDIM    250          // word(200)+tag(50)
#define HID     1024
#define NSP     8192         // spans per head
#define KS_     4
#define KL_     3
#define TSZ     (TT*HID)     // one P table
#define GDIR    32           // CTAs per LSTM direction
#define UPC     16           // units per CTA (512/32)

// ---------------- device scratch (static; no allocation allowed) ----------------
__device__ float g_x   [TT*XDIM];
__device__ float g_xg  [4*TT*NGATE];     // gate preactivations per direction
__device__ float g_P   [14*TSZ];         // factorized span tables
__device__ float g_loss;
__device__ unsigned g_gen;               // epoch counter (per launch/replay)
__device__ unsigned g_tktA, g_tktB;      // gemm tile tickets
// tagged h exchange buffers: slot = { f32 h (lo), u32 tag (hi) }
__device__ __align__(16) unsigned long long g_hxF[TT*UDIM];
__device__ __align__(16) unsigned long long g_hxB[TT*UDIM];

// ---------------- fast activations ----------------
__device__ __forceinline__ float fsigmoid(float x) {
    return __fdividef(1.f, 1.f + __expf(-x));
}
__device__ __forceinline__ float ftanh(float x) {
    return __fdividef(2.f, 1.f + __expf(-2.f * x)) - 1.f;
}

// verified tagged-slot pair load: data rides with tag in the same 8B word
__device__ __forceinline__ void ld_slot_pair(const unsigned long long* p, unsigned tg,
                                             float& o0, float& o1) {
    unsigned long long x, y;
    for (;;) {
        asm volatile("ld.volatile.global.v2.u64 {%0,%1}, [%2];"
                     : "=l"(x), "=l"(y) : "l"(p) : "memory");
        if ((unsigned)(x >> 32) >= tg && (unsigned)(y >> 32) >= tg) break;
    }
    o0 = __uint_as_float((unsigned)x);
    o1 = __uint_as_float((unsigned)y);
}

// ---------------- misc kernels ----------------
__global__ void build_x_kernel(const int* __restrict__ wi, const int* __restrict__ ti,
                               const float* __restrict__ Ww, const float* __restrict__ Wt) {
    int t = blockIdx.x;
    int j = threadIdx.x;
    if (t == 0 && j == 0) { g_loss = 0.f; g_gen += 1u; g_tktA = 0u; g_tktB = 0u; }
    if (j < 200)      g_x[t*XDIM + j] = Ww[(size_t)wi[t]*200 + j];
    else if (j < XDIM) g_x[t*XDIM + j] = Wt[(size_t)ti[t]*50 + (j - 200)];
}

__global__ void finalize_kernel(float* out) {
    out[0] = g_loss * (1.0f / 16384.0f);
}

// ---------------- standalone batched SGEMM (layer0 xg only) ----------------
struct GemmDesc {
    const float* A; const float* B; float* C; const float* bias;
    int M, N, K, lda, ldb, ldc;
};
struct GemmBatch { GemmDesc d[2]; };

__global__ void __launch_bounds__(256)
sgemm_kernel(GemmBatch batch)
{
    GemmDesc g = batch.d[blockIdx.z];
    const int m0 = blockIdx.y * 128;
    const int n0 = blockIdx.x * 128;
    if (m0 >= g.M || n0 >= g.N) return;

    __shared__ __align__(16) float As[16][132];
    __shared__ __align__(16) float Bs[16][132];

    const int tid = threadIdx.x;
    const int tx = tid & 15;
    const int ty = tid >> 4;

    unsigned long long acc2[8][4];
    #pragma unroll
    for (int i = 0; i < 8; i++)
        #pragma unroll
        for (int j = 0; j < 4; j++) acc2[i][j] = 0ull;

    const int lr = tid >> 1;
    const int lk = (tid & 1) * 8;

    for (int k0 = 0; k0 < g.K; k0 += 16) {
        {
            const float* ap = g.A + (size_t)(m0 + lr) * g.lda + k0 + lk;
            #pragma unroll
            for (int q = 0; q < 8; q++) {
                float v = (k0 + lk + q < g.K) ? ap[q] : 0.f;
                As[lk + q][lr] = v;
            }
            const float* bp = g.B + (size_t)(n0 + lr) * g.ldb + k0 + lk;
            #pragma unroll
            for (int q = 0; q < 8; q++) {
                float v = (k0 + lk + q < g.K) ? bp[q] : 0.f;
                Bs[lk + q][lr] = v;
            }
        }
        __syncthreads();

        #pragma unroll
        for (int kk = 0; kk < 16; kk++) {
            float a[8];
            *(float4*)&a[0] = *(const float4*)&As[kk][ty * 8];
            *(float4*)&a[4] = *(const float4*)&As[kk][ty * 8 + 4];
            const unsigned long long* bp = (const unsigned long long*)&Bs[kk][tx * 8];
            unsigned long long bv[4];
            #pragma unroll
            for (int j = 0; j < 4; j++) bv[j] = bp[j];
            #pragma unroll
            for (int i = 0; i < 8; i++) {
                unsigned long long av;
                asm("mov.b64 %0, {%1, %1};" : "=l"(av) : "f"(a[i]));
                #pragma unroll
                for (int j = 0; j < 4; j++)
                    asm("fma.rn.f32x2 %0, %1, %2, %0;" : "+l"(acc2[i][j]) : "l"(av), "l"(bv[j]));
            }
        }
        __syncthreads();
    }

    #pragma unroll
    for (int i = 0; i < 8; i++) {
        float* cp = g.C + (size_t)(m0 + ty * 8 + i) * g.ldc + n0 + tx * 8;
        float o[8];
        #pragma unroll
        for (int j = 0; j < 4; j++)
            asm("mov.b64 {%0, %1}, %2;" : "=f"(o[2*j]), "=f"(o[2*j+1]) : "l"(acc2[i][j]));
        if (g.bias) {
            #pragma unroll
            for (int j = 0; j < 8; j++) o[j] += g.bias[n0 + tx * 8 + j];
        }
        *(float4*)cp       = *(float4*)&o[0];
        *(float4*)(cp + 4) = *(float4*)&o[4];
    }
}

// ---------------- fused persistent kernel: LSTM CTAs + dependent GEMM CTAs ----------------
struct PTab {
    const float* B[14];
    float*       C[14];
    int          ldb[14];
};

__global__ void __launch_bounds__(512, 1)
fused_kernel(int phase,
             const float* __restrict__ xgF, const float* __restrict__ xgB,
             const float* __restrict__ WhhF, const float* __restrict__ WhhB,
             const float* __restrict__ WB0, const float* __restrict__ WB1,
             const float* __restrict__ bias0, const float* __restrict__ bias1,
             float* C0, float* C1, PTab pt)
{
    __shared__ __align__(16) float sA[16][136];   // GEMM: A tile
    __shared__ __align__(16) float sB[16][136];   // GEMM: B tile
    __shared__ __align__(16) float hsm[2][UDIM];  // LSTM: staged h (db)
    __shared__ __align__(16) float part[2][8][64];// LSTM: partials (db)
    __shared__ int smy;

    const int tid = threadIdx.x;
    const unsigned gen = g_gen;
    const unsigned base = ((gen * 2u + (unsigned)phase) << 10);

    if (blockIdx.x < 2 * GDIR) {
        // ================= LSTM role =================
        const int bid  = blockIdx.x;
        const bool back = (bid >= GDIR);
        const int dd    = back ? bid - GDIR : bid;

        const float* xg  = back ? xgB  : xgF;
        const float* Whh = back ? WhhB : WhhF;
        unsigned long long* hx = back ? g_hxB : g_hxF;

        const int wid   = tid >> 5;
        const int lane  = tid & 31;
        const int chunk = wid & 7;
        const int rg    = wid >> 3;
        const int row   = rg * 32 + lane;   // gate*16 + unit_local
        const int gate  = row >> 4;
        const int ul    = row & 15;
        const int u0    = dd * UPC;
        const int grow  = gate * UDIM + u0 + ul;

        unsigned long long w[32];
        {
            const ulonglong2* wp = (const ulonglong2*)(Whh + (size_t)grow * UDIM + chunk * 64);
            #pragma unroll
            for (int q = 0; q < 16; q++) {
                ulonglong2 v = wp[q];
                w[2*q]   = v.x;
                w[2*q+1] = v.y;
            }
        }

        // reduce/publish role: warps 14,15 (tid >= 448)
        const bool isred = (tid >= 448);
        const int rtid = tid - 448;
        const int ru  = rtid >> 2;           // unit 0..15
        const int rgt = rtid & 3;            // gate 0..3

        float c = 0.f;

        for (int s = 0; s < TT; s++) {
            const int t = back ? (TT - 1 - s) : s;
            const int p = s & 1;

            float xgv = 0.f;
            if (isred)
                xgv = __ldg(xg + (size_t)t * NGATE + rgt * UDIM + u0 + ru);

            unsigned long long a0 = 0ull, a1 = 0ull;
            if (s > 0) {
                const int tp = back ? t + 1 : t - 1;
                if (rg == 0) {
                    const unsigned long long* src = hx + (size_t)tp * UDIM + chunk * 64 + lane * 2;
                    const unsigned target = base + (unsigned)s;
                    unsigned long long x0, y0, x1, y1;
                    asm volatile("ld.volatile.global.v2.u64 {%0,%1}, [%2];"
                                 : "=l"(x0), "=l"(y0) : "l"(src) : "memory");
                    bool ok = ((unsigned)(x0 >> 32) >= target) && ((unsigned)(y0 >> 32) >= target);
                    if (!__all_sync(0xffffffffu, ok)) {
                        for (;;) {
                            asm volatile("ld.volatile.global.v2.u64 {%0,%1}, [%2];"
                                         : "=l"(x1), "=l"(y1) : "l"(src) : "memory");
                            ok = ((unsigned)(x0 >> 32) >= target) && ((unsigned)(y0 >> 32) >= target);
                            if (__all_sync(0xffffffffu, ok)) break;
                            asm volatile("ld.volatile.global.v2.u64 {%0,%1}, [%2];"
                                         : "=l"(x0), "=l"(y0) : "l"(src) : "memory");
                            ok = ((unsigned)(x1 >> 32) >= target) && ((unsigned)(y1 >> 32) >= target);
                            if (__all_sync(0xffffffffu, ok)) { x0 = x1; y0 = y1; break; }
                        }
                    }
                    float2 hv = make_float2(__uint_as_float((unsigned)x0),
                                            __uint_as_float((unsigned)y0));
                    *(float2*)&hsm[p][chunk * 64 + lane * 2] = hv;
                }
                asm volatile("bar.sync %0, 64;" :: "r"(chunk + 1) : "memory");

                const ulonglong2* hq = (const ulonglong2*)&hsm[p][chunk * 64];
                #pragma unroll
                for (int q = 0; q < 16; q++) {
                    ulonglong2 hv = hq[q];
                    asm("fma.rn.f32x2 %0, %1, %2, %0;" : "+l"(a0) : "l"(w[2*q]),   "l"(hv.x));
                    asm("fma.rn.f32x2 %0, %1, %2, %0;" : "+l"(a1) : "l"(w[2*q+1]), "l"(hv.y));
                }
            }
            float l0, h0, l1, h1;
            asm("mov.b64 {%0, %1}, %2;" : "=f"(l0), "=f"(h0) : "l"(a0));
            asm("mov.b64 {%0, %1}, %2;" : "=f"(l1), "=f"(h1) : "l"(a1));
            part[p][chunk][row] = (l0 + h0) + (l1 + h1);

            if (isred) {
                asm volatile("bar.sync 9, 512;" ::: "memory");
                const int prow = rgt * 16 + ru;
                float v = xgv;
                #pragma unroll
                for (int cc = 0; cc < 8; cc++) v += part[p][cc][prow];
                float v1 = __shfl_down_sync(0xffffffffu, v, 1);
                float v2 = __shfl_down_sync(0xffffffffu, v, 2);
                float v3 = __shfl_down_sync(0xffffffffu, v, 3);
                if (rgt == 0) {
                    float iv = fsigmoid(v);
                    float fv = fsigmoid(v1);
                    float gv = ftanh(v2);
                    float ov = fsigmoid(v3);
                    c = fv * c + iv * gv;
                    float h = ov * ftanh(c);
                    unsigned long long pkt = (unsigned long long)__float_as_uint(h)
                                           | ((unsigned long long)(base + (unsigned)s + 1u) << 32);
                    unsigned long long* dst = hx + (size_t)t * UDIM + u0 + ru;
                    asm volatile("st.relaxed.gpu.global.u64 [%0], %1;" :: "l"(dst), "l"(pkt) : "memory");
                }
            } else {
                asm volatile("bar.arrive 9, 512;" ::: "memory");
            }
        }
        return;
    }

    // ================= GEMM role =================
    const int NT = (phase == 0) ? 128 : 448;
    unsigned* tkt = (phase == 0) ? &g_tktA : &g_tktB;

    const int tx = tid & 15;
    const int ty = tid >> 4;          // 0..31
    const int lr = tid >> 2;          // 0..127
    const int lk4 = (tid & 3) * 4;

    for (;;) {
        if (tid == 0) smy = (int)atomicAdd(tkt, 1u);
        __syncthreads();
        const int my = smy;
        __syncthreads();
        if (my >= NT) return;

        int m0, n0, K, ldb, ldc, isfwd = 1;
        const float* Bw; float* C; const float* bias;

        if (phase == 0) {
            int cls = my >> 6, idx = my & 63;
            int dir = idx >> 5, r = idx & 31, mi = r >> 4;
            int mt = (cls == 0) ? (mi ? 2 : 1) : (mi ? 3 : 0);
            m0 = mt * 128; n0 = (r & 15) * 128;
            K = 1024; ldb = 1024; ldc = NGATE;
            Bw = dir ? WB1 : WB0;
            bias = dir ? bias1 : bias0;
            C = dir ? C1 : C0;
        } else {
            int cls = my / 112, idx = my % 112;
            int desc;
            if (idx < 56) {
                const int fl[7] = {0, 1, 2, 3, 8, 9, 10};
                desc = fl[idx >> 3]; m0 = cls * 128; isfwd = 1;
            } else {
                const int bl[7] = {4, 5, 6, 7, 11, 12, 13};
                desc = bl[(idx - 56) >> 3]; m0 = (3 - cls) * 128; isfwd = 0;
            }
            n0 = (idx & 7) * 128;
            K = 512; ldb = pt.ldb[desc]; ldc = HID;
            Bw = pt.B[desc]; C = pt.C[desc]; bias = nullptr;
        }

        // sentinel: wait until this tile's rows are (almost surely) published
        if (phase == 0) {
            const unsigned tgF = base + (unsigned)(m0 + 127) + 1u;
            const unsigned tgB = base + 512u - (unsigned)m0;
            volatile const unsigned long long* sf =
                (volatile const unsigned long long*)(g_hxF + (size_t)(m0 + 127) * UDIM + tid);
            volatile const unsigned long long* sb =
                (volatile const unsigned long long*)(g_hxB + (size_t)m0 * UDIM + tid);
            while (!(((unsigned)((*sf) >> 32) >= tgF) && ((unsigned)((*sb) >> 32) >= tgB)))
                __nanosleep(200);
        } else {
            const unsigned tg = isfwd ? (base + (unsigned)(m0 + 127) + 1u)
                                      : (base + 512u - (unsigned)m0);
            volatile const unsigned long long* sp = (volatile const unsigned long long*)
                ((isfwd ? g_hxF : g_hxB) + (size_t)(isfwd ? m0 + 127 : m0) * UDIM + tid);
            while (!((unsigned)((*sp) >> 32) >= tg))
                __nanosleep(200);
        }
        __syncthreads();

        unsigned long long acc2[4][4];
        #pragma unroll
        for (int i = 0; i < 4; i++)
            #pragma unroll
            for (int j = 0; j < 4; j++) acc2[i][j] = 0ull;

        const int t = m0 + lr;
        for (int k0 = 0; k0 < K; k0 += 16) {
            // A stage from tagged slots (per-slot verified)
            {
                const int unit = k0 + lk4;
                const unsigned long long* src; unsigned tg;
                if (phase == 0) {
                    if (unit < 512) { src = g_hxF + (size_t)t * UDIM + unit;       tg = base + t + 1; }
                    else            { src = g_hxB + (size_t)t * UDIM + unit - 512; tg = base + 512 - t; }
                } else {
                    src = (isfwd ? g_hxF : g_hxB) + (size_t)t * UDIM + unit;
                    tg = isfwd ? (base + t + 1) : (base + 512 - t);
                }
                float a0, a1, a2, a3;
                ld_slot_pair(src,     tg, a0, a1);
                ld_slot_pair(src + 2, tg, a2, a3);
                sA[lk4 + 0][lr] = a0;
                sA[lk4 + 1][lr] = a1;
                sA[lk4 + 2][lr] = a2;
                sA[lk4 + 3][lr] = a3;
            }
            // B stage (plain weights)
            {
                float4 bv = *(const float4*)(Bw + (size_t)(n0 + lr) * ldb + k0 + lk4);
                sB[lk4 + 0][lr] = bv.x;
                sB[lk4 + 1][lr] = bv.y;
                sB[lk4 + 2][lr] = bv.z;
                sB[lk4 + 3][lr] = bv.w;
            }
            __syncthreads();

            #pragma unroll
            for (int kk = 0; kk < 16; kk++) {
                float4 a4 = *(const float4*)&sA[kk][ty * 4];
                ulonglong2 b01 = *(const ulonglong2*)&sB[kk][tx * 8];
                ulonglong2 b23 = *(const ulonglong2*)&sB[kk][tx * 8 + 4];
                unsigned long long bv[4] = {b01.x, b01.y, b23.x, b23.y};
                float a[4] = {a4.x, a4.y, a4.z, a4.w};
                #pragma unroll
                for (int i = 0; i < 4; i++) {
                    unsigned long long av;
                    asm("mov.b64 %0, {%1, %1};" : "=l"(av) : "f"(a[i]));
                    #pragma unroll
                    for (int j = 0; j < 4; j++)
                        asm("fma.rn.f32x2 %0, %1, %2, %0;" : "+l"(acc2[i][j]) : "l"(av), "l"(bv[j]));
                }
            }
            __syncthreads();
        }

        #pragma unroll
        for (int i = 0; i < 4; i++) {
            float* cp = C + (size_t)(m0 + ty * 4 + i) * ldc + n0 + tx * 8;
            float o[8];
            #pragma unroll
            for (int j = 0; j < 4; j++)
                asm("mov.b64 {%0, %1}, %2;" : "=f"(o[2*j]), "=f"(o[2*j+1]) : "l"(acc2[i][j]));
            if (bias) {
                #pragma unroll
                for (int j = 0; j < 8; j++) o[j] += bias[n0 + tx * 8 + j];
            }
            *(float4*)cp       = *(float4*)&o[0];
            *(float4*)(cp + 4) = *(float4*)&o[4];
        }
    }
}

// ---------------- span loss: both heads in ONE launch (concurrent) ----------------
// blocks [0, NSP/8)          : struct head (KF=4, NC=2)
// blocks [NSP/8, 2*NSP/8)    : label head  (KF=3, NC=56)
struct SpanArgs {
    const int* lefts; const int* rights; const int* targets;
    const float* b1; const float* W2; const float* b2;
    int tabF, tabB;
};

template<int KF, int NC>
__device__ __forceinline__ float span_eval(const SpanArgs& sa, int warp, int lane)
{
    float4 acc[8];
    #pragma unroll
    for (int m = 0; m < 8; m++)
        acc[m] = *(const float4*)(sa.b1 + m * 128 + lane * 4);

    int ls[KF], rs[KF];
    #pragma unroll
    for (int k = 0; k < KF; k++) {
        ls[k] = __ldg(sa.lefts  + (size_t)warp * KF + k);
        rs[k] = __ldg(sa.rights + (size_t)warp * KF + k);
    }

    #pragma unroll
    for (int k = 0; k < KF; k++) {
        const float* Pf = g_P + (size_t)(sa.tabF + k) * TSZ;
        const float* Pb = g_P + (size_t)(sa.tabB + k) * TSZ;
        const float* r0 = Pf + (size_t)rs[k]       * HID + lane * 4;
        const float* r1 = Pf + (size_t)(ls[k] - 1) * HID + lane * 4;
        const float* r2 = Pb + (size_t)ls[k]       * HID + lane * 4;
        const float* r3 = Pb + (size_t)(rs[k] + 1) * HID + lane * 4;
        #pragma unroll
        for (int m = 0; m < 8; m++) {
            float4 va = __ldg((const float4*)(r0 + m * 128));
            float4 vb = __ldg((const float4*)(r1 + m * 128));
            float4 vc = __ldg((const float4*)(r2 + m * 128));
            float4 vd = __ldg((const float4*)(r3 + m * 128));
            acc[m].x += (va.x - vb.x) + (vc.x - vd.x);
            acc[m].y += (va.y - vb.y) + (vc.y - vd.y);
            acc[m].z += (va.z - vb.z) + (vc.z - vd.z);
            acc[m].w += (va.w - vb.w) + (vc.w - vd.w);
        }
    }
    #pragma unroll
    for (int m = 0; m < 8; m++) {
        acc[m].x = fmaxf(acc[m].x, 0.f);
        acc[m].y = fmaxf(acc[m].y, 0.f);
        acc[m].z = fmaxf(acc[m].z, 0.f);
        acc[m].w = fmaxf(acc[m].w, 0.f);
    }

    const int tgt = __ldg(sa.targets + warp);
    float mx = -1e30f, ssum = 0.f, sct = 0.f;
    for (int s = 0; s < NC; s++) {
        const float* wr = sa.W2 + (size_t)s * HID + lane * 4;
        float p = 0.f;
        #pragma unroll
        for (int m = 0; m < 8; m++) {
            float4 wv = __ldg((const float4*)(wr + m * 128));
            p += wv.x * acc[m].x + wv.y * acc[m].y + wv.z * acc[m].z + wv.w * acc[m].w;
        }
        p += __shfl_xor_sync(0xffffffffu, p, 1);
        p += __shfl_xor_sync(0xffffffffu, p, 2);
        p += __shfl_xor_sync(0xffffffffu, p, 4);
        p += __shfl_xor_sync(0xffffffffu, p, 8);
        p += __shfl_xor_sync(0xffffffffu, p, 16);
        p += sa.b2[s];
        if (s == tgt) sct = p;
        float m2 = fmaxf(mx, p);
        ssum = ssum * expf(mx - m2) + expf(p - m2);
        mx = m2;
    }
    return mx + logf(ssum) - sct;
}

__global__ void __launch_bounds__(256)
span_both_kernel(SpanArgs sa_s, SpanArgs sa_l)
{
    const int lane = threadIdx.x & 31;
    const int wInB = threadIdx.x >> 5;
    const int HB = NSP / 8;          // blocks per head

    float loss;
    if (blockIdx.x < HB) {
        const int warp = blockIdx.x * 8 + wInB;
        loss = span_eval<KS_, 2>(sa_s, warp, lane);
    } else {
        const int warp = (blockIdx.x - HB) * 8 + wInB;
        loss = span_eval<KL_, 56>(sa_l, warp, lane);
    }

    __shared__ float smloss[8];
    if (lane == 0) smloss[wInB] = loss;
    __syncthreads();
    if (threadIdx.x == 0) {
        float s = 0.f;
        #pragma unroll
        for (int q = 0; q < 8; q++) s += smloss[q];
        atomicAdd(&g_loss, s);
    }
}

// ---------------- host launch ----------------
extern "C" void kernel_launch(void* const* d_in, const int* in_sizes, int n_in,
                              void* d_out, int out_size)
{
    (void)n_in; (void)out_size;
    const int* wi = (const int*)d_in[0];
    const int* ti = (const int*)d_in[1];

    int isl, isr, ist, ill, ilr, ilt;
    if (in_sizes[2] == NSP) {
        ist = 2; ilt = 3; isl = 4; isr = 5; ill = 6; ilr = 7;
    } else {
        isl = 2; isr = 3; ist = 4; ill = 5; ilr = 6; ilt = 7;
    }

    const float* Wih[4] = {(const float*)d_in[10], (const float*)d_in[13],
                           (const float*)d_in[16], (const float*)d_in[19]};
    const float* Whh[4] = {(const float*)d_in[11], (const float*)d_in[14],
                           (const float*)d_in[17], (const float*)d_in[20]};
    const float* bb [4] = {(const float*)d_in[12], (const float*)d_in[15],
                           (const float*)d_in[18], (const float*)d_in[21]};
    const float* Ws1 = (const float*)d_in[22];
    const float* bs1 = (const float*)d_in[23];
    const float* Ws2 = (const float*)d_in[24];
    const float* bs2 = (const float*)d_in[25];
    const float* Wl1 = (const float*)d_in[26];
    const float* bl1 = (const float*)d_in[27];
    const float* Wl2 = (const float*)d_in[28];
    const float* bl2 = (const float*)d_in[29];

    float *px, *pxg, *pP;
    cudaGetSymbolAddress((void**)&px,  g_x);
    cudaGetSymbolAddress((void**)&pxg, g_xg);
    cudaGetSymbolAddress((void**)&pP,  g_P);

    build_x_kernel<<<TT, 256>>>(wi, ti, (const float*)d_in[8], (const float*)d_in[9]);

    // layer0 gate preactivations: xg = x @ Wih^T + b
    {
        GemmBatch gb = {};
        for (int d = 0; d < 2; d++)
            gb.d[d] = { px, Wih[d], pxg + (size_t)d * TT * NGATE, bb[d],
                        TT, NGATE, XDIM, XDIM, XDIM, NGATE };
        sgemm_kernel<<<dim3(16, 4, 2), 256>>>(gb);
    }

    PTab ptEmpty = {};
    // kernel A: L0 LSTM + xg1 GEMM (consumes tagged H0)
    fused_kernel<<<64 + 128, 512>>>(0,
        pxg, pxg + (size_t)TT * NGATE, Whh[0], Whh[1],
        Wih[2], Wih[3], bb[2], bb[3],
        pxg + (size_t)2 * TT * NGATE, pxg + (size_t)3 * TT * NGATE, ptEmpty);

    // kernel B: L1 LSTM + P-table GEMMs (consume tagged OUT)
    PTab pt = {};
    for (int k = 0; k < KS_; k++) {
        pt.B[k]      = Ws1 + k * 512;         pt.C[k]      = pP + (size_t)k * TSZ;        pt.ldb[k]      = 4096;
        pt.B[4 + k]  = Ws1 + 2048 + k * 512;  pt.C[4 + k]  = pP + (size_t)(4 + k) * TSZ;  pt.ldb[4 + k]  = 4096;
    }
    for (int k = 0; k < KL_; k++) {
        pt.B[8 + k]  = Wl1 + k * 512;         pt.C[8 + k]  = pP + (size_t)(8 + k) * TSZ;  pt.ldb[8 + k]  = 3072;
        pt.B[11 + k] = Wl1 + 1536 + k * 512;  pt.C[11 + k] = pP + (size_t)(11 + k) * TSZ; pt.ldb[11 + k] = 3072;
    }
    fused_kernel<<<64 + 448, 512>>>(1,
        pxg + (size_t)2 * TT * NGATE, pxg + (size_t)3 * TT * NGATE, Whh[2], Whh[3],
        nullptr, nullptr, nullptr, nullptr, nullptr, nullptr, pt);

    // both span heads in one launch -> run concurrently
    SpanArgs sa_s = { (const int*)d_in[isl], (const int*)d_in[isr], (const int*)d_in[ist],
                      bs1, Ws2, bs2, 0, 4 };
    SpanArgs sa_l = { (const int*)d_in[ill], (const int*)d_in[ilr], (const int*)d_in[ilt],
                      bl1, Wl2, bl2, 8, 11 };
    span_both_kernel<<<2 * (NSP / 8), 256>>>(sa_s, sa_l);

    finalize_kernel<<<1, 1>>>((float*)d_out);
}

// round 16
// speedup vs baseline: 1.0415x; 1.0031x over previous
#include <cuda_runtime.h>
#include <math.h>
#include <stdint.h>

// ---------------- problem constants ----------------
#define TT      512          // sequence length
#define UDIM    512          // LSTM hidden
#define NGATE   2048         // 4*U
#define XDIM    250          // word(200)+tag(50)
#define HID     1024
#define NSP     8192         // spans per head
#define KS_     4
#define KL_     3
#define TSZ     (TT*HID)     // one P table
#define GDIR    32           // CTAs per LSTM direction
#define UPC     16           // units per CTA (512/32)

// ---------------- device scratch (static; no allocation allowed) ----------------
__device__ float g_x   [TT*XDIM];
__device__ float g_xg  [4*TT*NGATE];     // gate preactivations per direction
__device__ float g_P   [14*TSZ];         // factorized span tables
__device__ float g_loss;
__device__ unsigned g_gen;               // epoch counter (per launch/replay)
__device__ unsigned g_tktA, g_tktB;      // gemm tile tickets
// tagged h exchange buffers: slot = { f32 h (lo), u32 tag (hi) }
__device__ __align__(16) unsigned long long g_hxF[TT*UDIM];
__device__ __align__(16) unsigned long long g_hxB[TT*UDIM];

// ---------------- fast activations ----------------
__device__ __forceinline__ float fsigmoid(float x) {
    return __fdividef(1.f, 1.f + __expf(-x));
}
__device__ __forceinline__ float ftanh(float x) {
    return __fdividef(2.f, 1.f + __expf(-2.f * x)) - 1.f;
}

// verified tagged-slot pair load: data rides with tag in the same 8B word
__device__ __forceinline__ void ld_slot_pair(const unsigned long long* p, unsigned tg,
                                             float& o0, float& o1) {
    unsigned long long x, y;
    for (;;) {
        asm volatile("ld.volatile.global.v2.u64 {%0,%1}, [%2];"
                     : "=l"(x), "=l"(y) : "l"(p) : "memory");
        if ((unsigned)(x >> 32) >= tg && (unsigned)(y >> 32) >= tg) break;
    }
    o0 = __uint_as_float((unsigned)x);
    o1 = __uint_as_float((unsigned)y);
}

// ---------------- misc kernels ----------------
__global__ void build_x_kernel(const int* __restrict__ wi, const int* __restrict__ ti,
                               const float* __restrict__ Ww, const float* __restrict__ Wt) {
    int t = blockIdx.x;
    int j = threadIdx.x;
    if (t == 0 && j == 0) { g_loss = 0.f; g_gen += 1u; g_tktA = 0u; g_tktB = 0u; }
    if (j < 200)      g_x[t*XDIM + j] = Ww[(size_t)wi[t]*200 + j];
    else if (j < XDIM) g_x[t*XDIM + j] = Wt[(size_t)ti[t]*50 + (j - 200)];
}

__global__ void finalize_kernel(float* out) {
    out[0] = g_loss * (1.0f / 16384.0f);
}

// ---------------- standalone batched SGEMM (layer0 xg only) ----------------
struct GemmDesc {
    const float* A; const float* B; float* C; const float* bias;
    int M, N, K, lda, ldb, ldc;
};
struct GemmBatch { GemmDesc d[2]; };

__global__ void __launch_bounds__(256)
sgemm_kernel(GemmBatch batch)
{
    GemmDesc g = batch.d[blockIdx.z];
    const int m0 = blockIdx.y * 128;
    const int n0 = blockIdx.x * 128;
    if (m0 >= g.M || n0 >= g.N) return;

    __shared__ __align__(16) float As[16][132];
    __shared__ __align__(16) float Bs[16][132];

    const int tid = threadIdx.x;
    const int tx = tid & 15;
    const int ty = tid >> 4;

    unsigned long long acc2[8][4];
    #pragma unroll
    for (int i = 0; i < 8; i++)
        #pragma unroll
        for (int j = 0; j < 4; j++) acc2[i][j] = 0ull;

    const int lr = tid >> 1;
    const int lk = (tid & 1) * 8;

    for (int k0 = 0; k0 < g.K; k0 += 16) {
        {
            const float* ap = g.A + (size_t)(m0 + lr) * g.lda + k0 + lk;
            #pragma unroll
            for (int q = 0; q < 8; q++) {
                float v = (k0 + lk + q < g.K) ? ap[q] : 0.f;
                As[lk + q][lr] = v;
            }
            const float* bp = g.B + (size_t)(n0 + lr) * g.ldb + k0 + lk;
            #pragma unroll
            for (int q = 0; q < 8; q++) {
                float v = (k0 + lk + q < g.K) ? bp[q] : 0.f;
                Bs[lk + q][lr] = v;
            }
        }
        __syncthreads();

        #pragma unroll
        for (int kk = 0; kk < 16; kk++) {
            float a[8];
            *(float4*)&a[0] = *(const float4*)&As[kk][ty * 8];
            *(float4*)&a[4] = *(const float4*)&As[kk][ty * 8 + 4];
            const unsigned long long* bp = (const unsigned long long*)&Bs[kk][tx * 8];
            unsigned long long bv[4];
            #pragma unroll
            for (int j = 0; j < 4; j++) bv[j] = bp[j];
            #pragma unroll
            for (int i = 0; i < 8; i++) {
                unsigned long long av;
                asm("mov.b64 %0, {%1, %1};" : "=l"(av) : "f"(a[i]));
                #pragma unroll
                for (int j = 0; j < 4; j++)
                    asm("fma.rn.f32x2 %0, %1, %2, %0;" : "+l"(acc2[i][j]) : "l"(av), "l"(bv[j]));
            }
        }
        __syncthreads();
    }

    #pragma unroll
    for (int i = 0; i < 8; i++) {
        float* cp = g.C + (size_t)(m0 + ty * 8 + i) * g.ldc + n0 + tx * 8;
        float o[8];
        #pragma unroll
        for (int j = 0; j < 4; j++)
            asm("mov.b64 {%0, %1}, %2;" : "=f"(o[2*j]), "=f"(o[2*j+1]) : "l"(acc2[i][j]));
        if (g.bias) {
            #pragma unroll
            for (int j = 0; j < 8; j++) o[j] += g.bias[n0 + tx * 8 + j];
        }
        *(float4*)cp       = *(float4*)&o[0];
        *(float4*)(cp + 4) = *(float4*)&o[4];
    }
}

// ---------------- fused persistent kernel: LSTM CTAs + dependent GEMM CTAs ----------------
struct PTab {
    const float* B[14];
    float*       C[14];
    int          ldb[14];
};

__global__ void __launch_bounds__(512, 1)
fused_kernel(int phase,
             const float* __restrict__ xgF, const float* __restrict__ xgB,
             const float* __restrict__ WhhF, const float* __restrict__ WhhB,
             const float* __restrict__ WB0, const float* __restrict__ WB1,
             const float* __restrict__ bias0, const float* __restrict__ bias1,
             float* C0, float* C1, PTab pt)
{
    __shared__ __align__(16) float sA[16][136];   // GEMM: A tile
    __shared__ __align__(16) float sB[16][136];   // GEMM: B tile
    __shared__ __align__(16) float hsm[2][UDIM];  // LSTM: staged h (db)
    __shared__ __align__(16) float part[2][8][64];// LSTM: partials (db)
    __shared__ int smy;

    const int tid = threadIdx.x;
    const unsigned gen = g_gen;
    const unsigned base = ((gen * 2u + (unsigned)phase) << 10);

    if (blockIdx.x < 2 * GDIR) {
        // ================= LSTM role =================
        const int bid  = blockIdx.x;
        const bool back = (bid >= GDIR);
        const int dd    = back ? bid - GDIR : bid;

        const float* xg  = back ? xgB  : xgF;
        const float* Whh = back ? WhhB : WhhF;
        unsigned long long* hx = back ? g_hxB : g_hxF;

        const int wid   = tid >> 5;
        const int lane  = tid & 31;
        const int chunk = wid & 7;
        const int rg    = wid >> 3;
        const int row   = rg * 32 + lane;   // gate*16 + unit_local
        const int gate  = row >> 4;
        const int ul    = row & 15;
        const int u0    = dd * UPC;
        const int grow  = gate * UDIM + u0 + ul;

        unsigned long long w[32];
        {
            const ulonglong2* wp = (const ulonglong2*)(Whh + (size_t)grow * UDIM + chunk * 64);
            #pragma unroll
            for (int q = 0; q < 16; q++) {
                ulonglong2 v = wp[q];
                w[2*q]   = v.x;
                w[2*q+1] = v.y;
            }
        }

        // reduce/publish role: warps 14,15 (tid >= 448)
        const bool isred = (tid >= 448);
        const int rtid = tid - 448;
        const int ru  = rtid >> 2;           // unit 0..15
        const int rgt = rtid & 3;            // gate 0..3 (i,f,g,o)

        float c = 0.f;

        for (int s = 0; s < TT; s++) {
            const int t = back ? (TT - 1 - s) : s;
            const int p = s & 1;

            float xgv = 0.f;
            if (isred)
                xgv = __ldg(xg + (size_t)t * NGATE + rgt * UDIM + u0 + ru);

            unsigned long long a0 = 0ull, a1 = 0ull;
            if (s > 0) {
                const int tp = back ? t + 1 : t - 1;
                if (rg == 0) {
                    const unsigned long long* src = hx + (size_t)tp * UDIM + chunk * 64 + lane * 2;
                    const unsigned target = base + (unsigned)s;
                    unsigned long long x0, y0, x1, y1;
                    asm volatile("ld.volatile.global.v2.u64 {%0,%1}, [%2];"
                                 : "=l"(x0), "=l"(y0) : "l"(src) : "memory");
                    bool ok = ((unsigned)(x0 >> 32) >= target) && ((unsigned)(y0 >> 32) >= target);
                    if (!__all_sync(0xffffffffu, ok)) {
                        for (;;) {
                            asm volatile("ld.volatile.global.v2.u64 {%0,%1}, [%2];"
                                         : "=l"(x1), "=l"(y1) : "l"(src) : "memory");
                            ok = ((unsigned)(x0 >> 32) >= target) && ((unsigned)(y0 >> 32) >= target);
                            if (__all_sync(0xffffffffu, ok)) break;
                            asm volatile("ld.volatile.global.v2.u64 {%0,%1}, [%2];"
                                         : "=l"(x0), "=l"(y0) : "l"(src) : "memory");
                            ok = ((unsigned)(x1 >> 32) >= target) && ((unsigned)(y1 >> 32) >= target);
                            if (__all_sync(0xffffffffu, ok)) { x0 = x1; y0 = y1; break; }
                        }
                    }
                    float2 hv = make_float2(__uint_as_float((unsigned)x0),
                                            __uint_as_float((unsigned)y0));
                    *(float2*)&hsm[p][chunk * 64 + lane * 2] = hv;
                }
                asm volatile("bar.sync %0, 64;" :: "r"(chunk + 1) : "memory");

                const ulonglong2* hq = (const ulonglong2*)&hsm[p][chunk * 64];
                #pragma unroll
                for (int q = 0; q < 16; q++) {
                    ulonglong2 hv = hq[q];
                    asm("fma.rn.f32x2 %0, %1, %2, %0;" : "+l"(a0) : "l"(w[2*q]),   "l"(hv.x));
                    asm("fma.rn.f32x2 %0, %1, %2, %0;" : "+l"(a1) : "l"(w[2*q+1]), "l"(hv.y));
                }
            }
            float l0, h0, l1, h1;
            asm("mov.b64 {%0, %1}, %2;" : "=f"(l0), "=f"(h0) : "l"(a0));
            asm("mov.b64 {%0, %1}, %2;" : "=f"(l1), "=f"(h1) : "l"(a1));
            part[p][chunk][row] = (l0 + h0) + (l1 + h1);

            if (isred) {
                asm volatile("bar.sync 9, 512;" ::: "memory");
                const int prow = rgt * 16 + ru;
                float v = xgv;
                #pragma unroll
                for (int cc = 0; cc < 8; cc++) v += part[p][cc][prow];
                // each lane applies ITS OWN gate's nonlinearity (branchless, one MUFU path)
                const bool isg = (rgt == 2);
                float xx = isg ? (2.f * v) : v;
                float r  = __fdividef(1.f, 1.f + __expf(-xx));
                float act = isg ? (2.f * r - 1.f) : r;   // tanh for gate g, sigmoid else
                float a1v = __shfl_down_sync(0xffffffffu, act, 1);
                float a2v = __shfl_down_sync(0xffffffffu, act, 2);
                float a3v = __shfl_down_sync(0xffffffffu, act, 3);
                if (rgt == 0) {
                    // act=i, a1v=f, a2v=g, a3v=o
                    c = a1v * c + act * a2v;
                    float h = a3v * ftanh(c);
                    unsigned long long pkt = (unsigned long long)__float_as_uint(h)
                                           | ((unsigned long long)(base + (unsigned)s + 1u) << 32);
                    unsigned long long* dst = hx + (size_t)t * UDIM + u0 + ru;
                    asm volatile("st.relaxed.gpu.global.u64 [%0], %1;" :: "l"(dst), "l"(pkt) : "memory");
                }
            } else {
                asm volatile("bar.arrive 9, 512;" ::: "memory");
            }
        }
        return;
    }

    // ================= GEMM role =================
    const int NT = (phase == 0) ? 128 : 448;
    unsigned* tkt = (phase == 0) ? &g_tktA : &g_tktB;

    const int tx = tid & 15;
    const int ty = tid >> 4;          // 0..31
    const int lr = tid >> 2;          // 0..127
    const int lk4 = (tid & 3) * 4;

    for (;;) {
        if (tid == 0) smy = (int)atomicAdd(tkt, 1u);
        __syncthreads();
        const int my = smy;
        __syncthreads();
        if (my >= NT) return;

        int m0, n0, K, ldb, ldc, isfwd = 1;
        const float* Bw; float* C; const float* bias;

        if (phase == 0) {
            int cls = my >> 6, idx = my & 63;
            int dir = idx >> 5, r = idx & 31, mi = r >> 4;
            int mt = (cls == 0) ? (mi ? 2 : 1) : (mi ? 3 : 0);
            m0 = mt * 128; n0 = (r & 15) * 128;
            K = 1024; ldb = 1024; ldc = NGATE;
            Bw = dir ? WB1 : WB0;
            bias = dir ? bias1 : bias0;
            C = dir ? C1 : C0;
        } else {
            int cls = my / 112, idx = my % 112;
            int desc;
            if (idx < 56) {
                const int fl[7] = {0, 1, 2, 3, 8, 9, 10};
                desc = fl[idx >> 3]; m0 = cls * 128; isfwd = 1;
            } else {
                const int bl[7] = {4, 5, 6, 7, 11, 12, 13};
                desc = bl[(idx - 56) >> 3]; m0 = (3 - cls) * 128; isfwd = 0;
            }
            n0 = (idx & 7) * 128;
            K = 512; ldb = pt.ldb[desc]; ldc = HID;
            Bw = pt.B[desc]; C = pt.C[desc]; bias = nullptr;
        }

        // sentinel: wait until this tile's rows are (almost surely) published
        if (phase == 0) {
            const unsigned tgF = base + (unsigned)(m0 + 127) + 1u;
            const unsigned tgB = base + 512u - (unsigned)m0;
            volatile const unsigned long long* sf =
                (volatile const unsigned long long*)(g_hxF + (size_t)(m0 + 127) * UDIM + tid);
            volatile const unsigned long long* sb =
                (volatile const unsigned long long*)(g_hxB + (size_t)m0 * UDIM + tid);
            while (!(((unsigned)((*sf) >> 32) >= tgF) && ((unsigned)((*sb) >> 32) >= tgB)))
                __nanosleep(200);
        } else {
            const unsigned tg = isfwd ? (base + (unsigned)(m0 + 127) + 1u)
                                      : (base + 512u - (unsigned)m0);
            volatile const unsigned long long* sp = (volatile const unsigned long long*)
                ((isfwd ? g_hxF : g_hxB) + (size_t)(isfwd ? m0 + 127 : m0) * UDIM + tid);
            while (!((unsigned)((*sp) >> 32) >= tg))
                __nanosleep(200);
        }
        __syncthreads();

        unsigned long long acc2[4][4];
        #pragma unroll
        for (int i = 0; i < 4; i++)
            #pragma unroll
            for (int j = 0; j < 4; j++) acc2[i][j] = 0ull;

        const int t = m0 + lr;
        for (int k0 = 0; k0 < K; k0 += 16) {
            // A stage from tagged slots (per-slot verified)
            {
                const int unit = k0 + lk4;
                const unsigned long long* src; unsigned tg;
                if (phase == 0) {
                    if (unit < 512) { src = g_hxF + (size_t)t * UDIM + unit;       tg = base + t + 1; }
                    else            { src = g_hxB + (size_t)t * UDIM + unit - 512; tg = base + 512 - t; }
                } else {
                    src = (isfwd ? g_hxF : g_hxB) + (size_t)t * UDIM + unit;
                    tg = isfwd ? (base + t + 1) : (base + 512 - t);
                }
                float a0, a1, a2, a3;
                ld_slot_pair(src,     tg, a0, a1);
                ld_slot_pair(src + 2, tg, a2, a3);
                sA[lk4 + 0][lr] = a0;
                sA[lk4 + 1][lr] = a1;
                sA[lk4 + 2][lr] = a2;
                sA[lk4 + 3][lr] = a3;
            }
            // B stage (plain weights)
            {
                float4 bv = *(const float4*)(Bw + (size_t)(n0 + lr) * ldb + k0 + lk4);
                sB[lk4 + 0][lr] = bv.x;
                sB[lk4 + 1][lr] = bv.y;
                sB[lk4 + 2][lr] = bv.z;
                sB[lk4 + 3][lr] = bv.w;
            }
            __syncthreads();

            #pragma unroll
            for (int kk = 0; kk < 16; kk++) {
                float4 a4 = *(const float4*)&sA[kk][ty * 4];
                ulonglong2 b01 = *(const ulonglong2*)&sB[kk][tx * 8];
                ulonglong2 b23 = *(const ulonglong2*)&sB[kk][tx * 8 + 4];
                unsigned long long bv[4] = {b01.x, b01.y, b23.x, b23.y};
                float a[4] = {a4.x, a4.y, a4.z, a4.w};
                #pragma unroll
                for (int i = 0; i < 4; i++) {
                    unsigned long long av;
                    asm("mov.b64 %0, {%1, %1};" : "=l"(av) : "f"(a[i]));
                    #pragma unroll
                    for (int j = 0; j < 4; j++)
                        asm("fma.rn.f32x2 %0, %1, %2, %0;" : "+l"(acc2[i][j]) : "l"(av), "l"(bv[j]));
                }
            }
            __syncthreads();
        }

        #pragma unroll
        for (int i = 0; i < 4; i++) {
            float* cp = C + (size_t)(m0 + ty * 4 + i) * ldc + n0 + tx * 8;
            float o[8];
            #pragma unroll
            for (int j = 0; j < 4; j++)
                asm("mov.b64 {%0, %1}, %2;" : "=f"(o[2*j]), "=f"(o[2*j+1]) : "l"(acc2[i][j]));
            if (bias) {
                #pragma unroll
                for (int j = 0; j < 8; j++) o[j] += bias[n0 + tx * 8 + j];
            }
            *(float4*)cp       = *(float4*)&o[0];
            *(float4*)(cp + 4) = *(float4*)&o[4];
        }
    }
}

// ---------------- span loss: both heads in ONE launch (concurrent) ----------------
struct SpanArgs {
    const int* lefts; const int* rights; const int* targets;
    const float* b1; const float* W2; const float* b2;
    int tabF, tabB;
};

template<int KF, int NC>
__device__ __forceinline__ float span_eval(const SpanArgs& sa, int warp, int lane)
{
    float4 acc[8];
    #pragma unroll
    for (int m = 0; m < 8; m++)
        acc[m] = *(const float4*)(sa.b1 + m * 128 + lane * 4);

    int ls[KF], rs[KF];
    #pragma unroll
    for (int k = 0; k < KF; k++) {
        ls[k] = __ldg(sa.lefts  + (size_t)warp * KF + k);
        rs[k] = __ldg(sa.rights + (size_t)warp * KF + k);
    }

    #pragma unroll
    for (int k = 0; k < KF; k++) {
        const float* Pf = g_P + (size_t)(sa.tabF + k) * TSZ;
        const float* Pb = g_P + (size_t)(sa.tabB + k) * TSZ;
        const float* r0 = Pf + (size_t)rs[k]       * HID + lane * 4;
        const float* r1 = Pf + (size_t)(ls[k] - 1) * HID + lane * 4;
        const float* r2 = Pb + (size_t)ls[k]       * HID + lane * 4;
        const float* r3 = Pb + (size_t)(rs[k] + 1) * HID + lane * 4;
        #pragma unroll
        for (int m = 0; m < 8; m++) {
            float4 va = __ldg((const float4*)(r0 + m * 128));
            float4 vb = __ldg((const float4*)(r1 + m * 128));
            float4 vc = __ldg((const float4*)(r2 + m * 128));
            float4 vd = __ldg((const float4*)(r3 + m * 128));
            acc[m].x += (va.x - vb.x) + (vc.x - vd.x);
            acc[m].y += (va.y - vb.y) + (vc.y - vd.y);
            acc[m].z += (va.z - vb.z) + (vc.z - vd.z);
            acc[m].w += (va.w - vb.w) + (vc.w - vd.w);
        }
    }
    #pragma unroll
    for (int m = 0; m < 8; m++) {
        acc[m].x = fmaxf(acc[m].x, 0.f);
        acc[m].y = fmaxf(acc[m].y, 0.f);
        acc[m].z = fmaxf(acc[m].z, 0.f);
        acc[m].w = fmaxf(acc[m].w, 0.f);
    }

    const int tgt = __ldg(sa.targets + warp);
    float mx = -1e30f, ssum = 0.f, sct = 0.f;
    for (int s = 0; s < NC; s++) {
        const float* wr = sa.W2 + (size_t)s * HID + lane * 4;
        float p = 0.f;
        #pragma unroll
        for (int m = 0; m < 8; m++) {
            float4 wv = __ldg((const float4*)(wr + m * 128));
            p += wv.x * acc[m].x + wv.y * acc[m].y + wv.z * acc[m].z + wv.w * acc[m].w;
        }
        p += __shfl_xor_sync(0xffffffffu, p, 1);
        p += __shfl_xor_sync(0xffffffffu, p, 2);
        p += __shfl_xor_sync(0xffffffffu, p, 4);
        p += __shfl_xor_sync(0xffffffffu, p, 8);
        p += __shfl_xor_sync(0xffffffffu, p, 16);
        p += sa.b2[s];
        if (s == tgt) sct = p;
        float m2 = fmaxf(mx, p);
        ssum = ssum * expf(mx - m2) + expf(p - m2);
        mx = m2;
    }
    return mx + logf(ssum) - sct;
}

__global__ void __launch_bounds__(256)
span_both_kernel(SpanArgs sa_s, SpanArgs sa_l)
{
    const int lane = threadIdx.x & 31;
    const int wInB = threadIdx.x >> 5;
    const int HB = NSP / 8;          // blocks per head

    float loss;
    if (blockIdx.x < HB) {
        const int warp = blockIdx.x * 8 + wInB;
        loss = span_eval<KS_, 2>(sa_s, warp, lane);
    } else {
        const int warp = (blockIdx.x - HB) * 8 + wInB;
        loss = span_eval<KL_, 56>(sa_l, warp, lane);
    }

    __shared__ float smloss[8];
    if (lane == 0) smloss[wInB] = loss;
    __syncthreads();
    if (threadIdx.x == 0) {
        float s = 0.f;
        #pragma unroll
        for (int q = 0; q < 8; q++) s += smloss[q];
        atomicAdd(&g_loss, s);
    }
}

// ---------------- host launch ----------------
extern "C" void kernel_launch(void* const* d_in, const int* in_sizes, int n_in,
                              void* d_out, int out_size)
{
    (void)n_in; (void)out_size;
    const int* wi = (const int*)d_in[0];
    const int* ti = (const int*)d_in[1];

    int isl, isr, ist, ill, ilr, ilt;
    if (in_sizes[2] == NSP) {
        ist = 2; ilt = 3; isl = 4; isr = 5; ill = 6; ilr = 7;
    } else {
        isl = 2; isr = 3; ist = 4; ill = 5; ilr = 6; ilt = 7;
    }

    const float* Wih[4] = {(const float*)d_in[10], (const float*)d_in[13],
                           (const float*)d_in[16], (const float*)d_in[19]};
    const float* Whh[4] = {(const float*)d_in[11], (const float*)d_in[14],
                           (const float*)d_in[17], (const float*)d_in[20]};
    const float* bb [4] = {(const float*)d_in[12], (const float*)d_in[15],
                           (const float*)d_in[18], (const float*)d_in[21]};
    const float* Ws1 = (const float*)d_in[22];
    const float* bs1 = (const float*)d_in[23];
    const float* Ws2 = (const float*)d_in[24];
    const float* bs2 = (const float*)d_in[25];
    const float* Wl1 = (const float*)d_in[26];
    const float* bl1 = (const float*)d_in[27];
    const float* Wl2 = (const float*)d_in[28];
    const float* bl2 = (const float*)d_in[29];

    float *px, *pxg, *pP;
    cudaGetSymbolAddress((void**)&px,  g_x);
    cudaGetSymbolAddress((void**)&pxg, g_xg);
    cudaGetSymbolAddress((void**)&pP,  g_P);

    build_x_kernel<<<TT, 256>>>(wi, ti, (const float*)d_in[8], (const float*)d_in[9]);

    // layer0 gate preactivations: xg = x @ Wih^T + b
    {
        GemmBatch gb = {};
        for (int d = 0; d < 2; d++)
            gb.d[d] = { px, Wih[d], pxg + (size_t)d * TT * NGATE, bb[d],
                        TT, NGATE, XDIM, XDIM, XDIM, NGATE };
        sgemm_kernel<<<dim3(16, 4, 2), 256>>>(gb);
    }

    PTab ptEmpty = {};
    // kernel A: L0 LSTM + xg1 GEMM (consumes tagged H0)
    fused_kernel<<<64 + 128, 512>>>(0,
        pxg, pxg + (size_t)TT * NGATE, Whh[0], Whh[1],
        Wih[2], Wih[3], bb[2], bb[3],
        pxg + (size_t)2 * TT * NGATE, pxg + (size_t)3 * TT * NGATE, ptEmpty);

    // kernel B: L1 LSTM + P-table GEMMs (consume tagged OUT)
    PTab pt = {};
    for (int k = 0; k < KS_; k++) {
        pt.B[k]      = Ws1 + k * 512;         pt.C[k]      = pP + (size_t)k * TSZ;        pt.ldb[k]      = 4096;
        pt.B[4 + k]  = Ws1 + 2048 + k * 512;  pt.C[4 + k]  = pP + (size_t)(4 + k) * TSZ;  pt.ldb[4 + k]  = 4096;
    }
    for (int k = 0; k < KL_; k++) {
        pt.B[8 + k]  = Wl1 + k * 512;         pt.C[8 + k]  = pP + (size_t)(8 + k) * TSZ;  pt.ldb[8 + k]  = 3072;
        pt.B[11 + k] = Wl1 + 1536 + k * 512;  pt.C[11 + k] = pP + (size_t)(11 + k) * TSZ; pt.ldb[11 + k] = 3072;
    }
    fused_kernel<<<64 + 448, 512>>>(1,
        pxg + (size_t)2 * TT * NGATE, pxg + (size_t)3 * TT * NGATE, Whh[2], Whh[3],
        nullptr, nullptr, nullptr, nullptr, nullptr, nullptr, pt);

    // both span heads in one launch -> run concurrently
    SpanArgs sa_s = { (const int*)d_in[isl], (const int*)d_in[isr], (const int*)d_in[ist],
                      bs1, Ws2, bs2, 0, 4 };
    SpanArgs sa_l = { (const int*)d_in[ill], (const int*)d_in[ilr], (const int*)d_in[ilt],
                      bl1, Wl2, bl2, 8, 11 };
    span_both_kernel<<<2 * (NSP / 8), 256>>>(sa_s, sa_l);

    finalize_kernel<<<1, 1>>>((float*)d_out);
}